// round 1
// baseline (speedup 1.0000x reference)
#include <cuda_runtime.h>
#include <cuda_bf16.h>
#include <math.h>

#define NA 50000
#define NP 100000
#define DA 512
#define DP 256
#define HID 64
#define NOUT 16
#define NE 2000000

// ---------------- scratch (static device allocations are the sanctioned path) ----
__device__ float g_xa[NA * HID];          // relu(x_a @ fc1_a_w + b)
__device__ float g_xp[NP * HID];
__device__ float g_ha[2 * NA * HID];      // double-buffered hidden states
__device__ float g_hp[2 * NP * HID];

__device__ int g_rp_ap[NA + 1];
__device__ int g_rp_pa[NP + 1];
__device__ int g_rp_pp[NP + 1];
__device__ int g_ts_ap[NE];
__device__ int g_ts_pa[NE];
__device__ int g_ts_pp[NE];
__device__ int g_cntA[NA];
__device__ int g_cntP1[NP];
__device__ int g_cntP2[NP];

// per-hop scalar projections
__device__ float g_x1ap[NA], g_x2ap[NA], g_h1pa[NA];
__device__ float g_x1pa[NP], g_x2pa[NP], g_x1pp[NP], g_x2pp[NP], g_h1ap[NP], g_h1pp[NP];

// ---------------- helpers ----------------
__device__ __forceinline__ const float* bufA_c(int c) {
    return (c == 2) ? g_xa : (g_ha + (size_t)c * NA * HID);
}
__device__ __forceinline__ const float* bufP_c(int c) {
    return (c == 2) ? g_xp : (g_hp + (size_t)c * NP * HID);
}
__device__ __forceinline__ float eluf(float v) {
    return v > 0.f ? v : expm1f(v);
}
__device__ __forceinline__ float lrelu_exp(float sc) {
    sc = sc >= 0.f ? sc : 0.2f * sc;
    return __expf(sc);
}
__device__ __forceinline__ float wred(float v) {
    v += __shfl_down_sync(0xffffffffu, v, 16);
    v += __shfl_down_sync(0xffffffffu, v, 8);
    v += __shfl_down_sync(0xffffffffu, v, 4);
    v += __shfl_down_sync(0xffffffffu, v, 2);
    v += __shfl_down_sync(0xffffffffu, v, 1);
    return v;
}

// ---------------- CSR build ----------------
__global__ void zero_cnt_kernel() {
    int i = blockIdx.x * blockDim.x + threadIdx.x;
    int stride = gridDim.x * blockDim.x;
    for (; i < NA + 2 * NP; i += stride) {
        if (i < NA) g_cntA[i] = 0;
        else if (i < NA + NP) g_cntP1[i - NA] = 0;
        else g_cntP2[i - NA - NP] = 0;
    }
}

__global__ void hist_kernel(const int* __restrict__ ap_s,
                            const int* __restrict__ pa_s,
                            const int* __restrict__ pp_s) {
    int i = blockIdx.x * blockDim.x + threadIdx.x;
    int stride = gridDim.x * blockDim.x;
    for (; i < 3 * NE; i += stride) {
        if (i < NE) atomicAdd(&g_cntA[ap_s[i]], 1);
        else if (i < 2 * NE) atomicAdd(&g_cntP1[pa_s[i - NE]], 1);
        else atomicAdd(&g_cntP2[pp_s[i - 2 * NE]], 1);
    }
}

// one block per edge type; 1024 threads sequential-chunk exclusive scan
__global__ void scan_kernel() {
    const int* cnt; int* rp; int n;
    if (blockIdx.x == 0)      { cnt = g_cntA;  rp = g_rp_ap; n = NA; }
    else if (blockIdx.x == 1) { cnt = g_cntP1; rp = g_rp_pa; n = NP; }
    else                      { cnt = g_cntP2; rp = g_rp_pp; n = NP; }

    __shared__ int wsum[32];
    int tid = threadIdx.x, lane = tid & 31, wid = tid >> 5;
    int carry = 0;
    for (int base = 0; base < n; base += 1024) {
        int i = base + tid;
        int v = (i < n) ? cnt[i] : 0;
        int x = v;
        #pragma unroll
        for (int off = 1; off < 32; off <<= 1) {
            int y = __shfl_up_sync(0xffffffffu, x, off);
            if (lane >= off) x += y;
        }
        if (lane == 31) wsum[wid] = x;
        __syncthreads();
        if (wid == 0) {
            int s = wsum[lane];
            #pragma unroll
            for (int off = 1; off < 32; off <<= 1) {
                int y = __shfl_up_sync(0xffffffffu, s, off);
                if (lane >= off) s += y;
            }
            wsum[lane] = s;
        }
        __syncthreads();
        int woff = wid ? wsum[wid - 1] : 0;
        if (i < n) rp[i] = carry + woff + x - v;   // exclusive
        int total = wsum[31];
        __syncthreads();
        carry += total;
    }
    if (tid == 0) rp[n] = carry;
}

__global__ void scatter_kernel(const int* __restrict__ ap_s, const int* __restrict__ ap_t,
                               const int* __restrict__ pa_s, const int* __restrict__ pa_t,
                               const int* __restrict__ pp_s, const int* __restrict__ pp_t) {
    int i = blockIdx.x * blockDim.x + threadIdx.x;
    int stride = gridDim.x * blockDim.x;
    for (; i < 3 * NE; i += stride) {
        if (i < NE) {
            int s = ap_s[i];
            int pos = g_rp_ap[s] + atomicAdd(&g_cntA[s], 1);
            g_ts_ap[pos] = ap_t[i];
        } else if (i < 2 * NE) {
            int e = i - NE;
            int s = pa_s[e];
            int pos = g_rp_pa[s] + atomicAdd(&g_cntP1[s], 1);
            g_ts_pa[pos] = pa_t[e];
        } else {
            int e = i - 2 * NE;
            int s = pp_s[e];
            int pos = g_rp_pp[s] + atomicAdd(&g_cntP2[s], 1);
            g_ts_pp[pos] = pp_t[e];
        }
    }
}

// ---------------- input projection GEMM: Y = relu(X[N,K] @ W[K,64] + b) ----------
// 256 threads, 4x4 register tile, block covers 64 nodes x 64 cols.
__global__ void proj_gemm_kernel(const float* __restrict__ X,
                                 const float* __restrict__ W,
                                 const float* __restrict__ bias,
                                 int N, int K, int sel /*0: g_xa, 1: g_xp*/) {
    __shared__ __align__(16) float xs[32 * 68];
    __shared__ __align__(16) float ws[32 * 64];
    float* Y = sel ? g_xp : g_xa;

    int tid = threadIdx.x;
    int tc = tid & 15;       // col group: cols 4*tc..4*tc+3
    int tr = tid >> 4;       // row group: nodes nb+4*tr..+3
    int nb = blockIdx.x * 64;

    float acc[16];
    #pragma unroll
    for (int i = 0; i < 16; i++) acc[i] = 0.f;

    for (int kc = 0; kc < K; kc += 32) {
        #pragma unroll
        for (int j = 0; j < 8; j++) {
            int idx = tid + 256 * j;           // 0..2047
            int k = idx >> 6, col = idx & 63;
            ws[k * 64 + col] = W[(size_t)(kc + k) * 64 + col];
        }
        #pragma unroll
        for (int j = 0; j < 8; j++) {
            int idx = tid + 256 * j;
            int k = idx & 31, nn = idx >> 5;   // nn 0..63
            int n = nb + nn;
            xs[k * 68 + nn] = (n < N) ? X[(size_t)n * K + kc + k] : 0.f;
        }
        __syncthreads();
        #pragma unroll
        for (int kk = 0; kk < 32; kk++) {
            float4 wv = *reinterpret_cast<const float4*>(&ws[kk * 64 + (tc << 2)]);
            float4 xv = *reinterpret_cast<const float4*>(&xs[kk * 68 + (tr << 2)]);
            acc[0]  = fmaf(xv.x, wv.x, acc[0]);
            acc[1]  = fmaf(xv.x, wv.y, acc[1]);
            acc[2]  = fmaf(xv.x, wv.z, acc[2]);
            acc[3]  = fmaf(xv.x, wv.w, acc[3]);
            acc[4]  = fmaf(xv.y, wv.x, acc[4]);
            acc[5]  = fmaf(xv.y, wv.y, acc[5]);
            acc[6]  = fmaf(xv.y, wv.z, acc[6]);
            acc[7]  = fmaf(xv.y, wv.w, acc[7]);
            acc[8]  = fmaf(xv.z, wv.x, acc[8]);
            acc[9]  = fmaf(xv.z, wv.y, acc[9]);
            acc[10] = fmaf(xv.z, wv.z, acc[10]);
            acc[11] = fmaf(xv.z, wv.w, acc[11]);
            acc[12] = fmaf(xv.w, wv.x, acc[12]);
            acc[13] = fmaf(xv.w, wv.y, acc[13]);
            acc[14] = fmaf(xv.w, wv.z, acc[14]);
            acc[15] = fmaf(xv.w, wv.w, acc[15]);
        }
        __syncthreads();
    }

    float4 bv = *reinterpret_cast<const float4*>(&bias[tc << 2]);
    #pragma unroll
    for (int i = 0; i < 4; i++) {
        int n = nb + (tr << 2) + i;
        if (n < N) {
            float4 r;
            r.x = fmaxf(acc[i * 4 + 0] + bv.x, 0.f);
            r.y = fmaxf(acc[i * 4 + 1] + bv.y, 0.f);
            r.z = fmaxf(acc[i * 4 + 2] + bv.z, 0.f);
            r.w = fmaxf(acc[i * 4 + 3] + bv.w, 0.f);
            *reinterpret_cast<float4*>(&Y[(size_t)n * 64 + (tc << 2)]) = r;
        }
    }
}

// ---------------- per-hop scalar projections ----------------
// a-nodes: x1ap = xa.a1_ap, x2ap = xa.a2_ap, h1pa = h_a.a2_pa
__global__ void sprojA_kernel(const float* __restrict__ a1ap,
                              const float* __restrict__ a2ap,
                              const float* __restrict__ a2pa, int curA) {
    int w = (blockIdx.x * blockDim.x + threadIdx.x) >> 5;
    int lane = threadIdx.x & 31;
    int nw = (gridDim.x * blockDim.x) >> 5;
    const float* h = bufA_c(curA);
    float va0 = a1ap[lane], va1 = a1ap[lane + 32];
    float vb0 = a2ap[lane], vb1 = a2ap[lane + 32];
    float vc0 = a2pa[lane], vc1 = a2pa[lane + 32];
    for (int n = w; n < NA; n += nw) {
        float x0 = g_xa[(size_t)n * 64 + lane], x1 = g_xa[(size_t)n * 64 + 32 + lane];
        float h0 = h[(size_t)n * 64 + lane],    h1 = h[(size_t)n * 64 + 32 + lane];
        float d1 = wred(fmaf(x0, va0, x1 * va1));
        float d2 = wred(fmaf(x0, vb0, x1 * vb1));
        float d3 = wred(fmaf(h0, vc0, h1 * vc1));
        if (lane == 0) { g_x1ap[n] = d1; g_x2ap[n] = d2; g_h1pa[n] = d3; }
    }
}

// p-nodes: x1pa,x2pa,x1pp,x2pp from xp; h1ap = h_p.a2_ap, h1pp = h_p.a2_pp
__global__ void sprojP_kernel(const float* __restrict__ a1pa, const float* __restrict__ a2pa,
                              const float* __restrict__ a1pp, const float* __restrict__ a2pp,
                              const float* __restrict__ a2ap, int curP) {
    int w = (blockIdx.x * blockDim.x + threadIdx.x) >> 5;
    int lane = threadIdx.x & 31;
    int nw = (gridDim.x * blockDim.x) >> 5;
    const float* h = bufP_c(curP);
    float v10 = a1pa[lane], v11 = a1pa[lane + 32];
    float v20 = a2pa[lane], v21 = a2pa[lane + 32];
    float v30 = a1pp[lane], v31 = a1pp[lane + 32];
    float v40 = a2pp[lane], v41 = a2pp[lane + 32];
    float v50 = a2ap[lane], v51 = a2ap[lane + 32];
    for (int n = w; n < NP; n += nw) {
        float x0 = g_xp[(size_t)n * 64 + lane], x1 = g_xp[(size_t)n * 64 + 32 + lane];
        float h0 = h[(size_t)n * 64 + lane],    h1 = h[(size_t)n * 64 + 32 + lane];
        float d1 = wred(fmaf(x0, v10, x1 * v11));
        float d2 = wred(fmaf(x0, v20, x1 * v21));
        float d3 = wred(fmaf(x0, v30, x1 * v31));
        float d4 = wred(fmaf(x0, v40, x1 * v41));
        float d5 = wred(fmaf(h0, v50, h1 * v51));
        float d6 = wred(fmaf(h0, v41 == v41 ? v40 : v40, h1 * v41)); // h_p.a2_pp
        if (lane == 0) {
            g_x1pa[n] = d1; g_x2pa[n] = d2; g_x1pp[n] = d3; g_x2pp[n] = d4;
            g_h1ap[n] = d5; g_h1pp[n] = d6;
        }
    }
}

// ---------------- edge aggregation ----------------
__device__ __forceinline__ void relation_accum(const int* __restrict__ rp,
                                               const int* __restrict__ ts,
                                               const float* __restrict__ h,
                                               const float* __restrict__ h1arr,
                                               float x1, int n, int sub,
                                               float4& acc, float& div) {
    int e = rp[n], end = rp[n + 1];
    #pragma unroll 4
    for (; e < end; ++e) {
        int t = __ldg(&ts[e]);
        float w = lrelu_exp(x1 + __ldg(&h1arr[t]));
        const float4 hv = *reinterpret_cast<const float4*>(&h[(size_t)t * 64 + (sub << 2)]);
        acc.x = fmaf(w, hv.x, acc.x);
        acc.y = fmaf(w, hv.y, acc.y);
        acc.z = fmaf(w, hv.z, acc.z);
        acc.w = fmaf(w, hv.w, acc.w);
        div += w;
    }
}

__global__ void aggA_kernel(int curP, int nextA) {
    int lane = threadIdx.x & 31;
    int sub = lane & 15;
    int half = lane >> 4;
    int warp = (blockIdx.x * blockDim.x + threadIdx.x) >> 5;
    int nwarps = (gridDim.x * blockDim.x) >> 5;
    const float* __restrict__ h = bufP_c(curP);
    float* __restrict__ out = g_ha + (size_t)nextA * NA * HID;
    for (int n0 = warp * 2; n0 < NA; n0 += nwarps * 2) {
        int n = n0 + half;
        if (n >= NA) continue;
        float x1 = g_x1ap[n];
        float4 acc = {0.f, 0.f, 0.f, 0.f};
        float div = 0.f;
        relation_accum(g_rp_ap, g_ts_ap, h, g_h1ap, x1, n, sub, acc, div);
        float w2 = lrelu_exp(x1 + g_x2ap[n]);
        const float4 xv = *reinterpret_cast<const float4*>(&g_xa[(size_t)n * 64 + (sub << 2)]);
        acc.x = fmaf(w2, xv.x, acc.x);
        acc.y = fmaf(w2, xv.y, acc.y);
        acc.z = fmaf(w2, xv.z, acc.z);
        acc.w = fmaf(w2, xv.w, acc.w);
        div += w2;
        float inv = 1.f / div;
        float4 r;
        r.x = eluf(acc.x * inv);
        r.y = eluf(acc.y * inv);
        r.z = eluf(acc.z * inv);
        r.w = eluf(acc.w * inv);
        *reinterpret_cast<float4*>(&out[(size_t)n * 64 + (sub << 2)]) = r;
    }
}

__global__ void aggP_kernel(int curA, int curP, int nextP) {
    int lane = threadIdx.x & 31;
    int sub = lane & 15;
    int half = lane >> 4;
    int warp = (blockIdx.x * blockDim.x + threadIdx.x) >> 5;
    int nwarps = (gridDim.x * blockDim.x) >> 5;
    const float* __restrict__ hA = bufA_c(curA);
    const float* __restrict__ hP = bufP_c(curP);
    float* __restrict__ out = g_hp + (size_t)nextP * NP * HID;
    for (int n0 = warp * 2; n0 < NP; n0 += nwarps * 2) {
        int n = n0 + half;
        if (n >= NP) continue;
        float x1a = g_x1pa[n];
        float x1p = g_x1pp[n];
        float4 acc1 = {0.f, 0.f, 0.f, 0.f}, acc2 = {0.f, 0.f, 0.f, 0.f};
        float div1 = 0.f, div2 = 0.f;
        relation_accum(g_rp_pa, g_ts_pa, hA, g_h1pa, x1a, n, sub, acc1, div1);
        relation_accum(g_rp_pp, g_ts_pp, hP, g_h1pp, x1p, n, sub, acc2, div2);
        const float4 xv = *reinterpret_cast<const float4*>(&g_xp[(size_t)n * 64 + (sub << 2)]);
        float w2a = lrelu_exp(x1a + g_x2pa[n]);
        float w2p = lrelu_exp(x1p + g_x2pp[n]);
        acc1.x = fmaf(w2a, xv.x, acc1.x); acc1.y = fmaf(w2a, xv.y, acc1.y);
        acc1.z = fmaf(w2a, xv.z, acc1.z); acc1.w = fmaf(w2a, xv.w, acc1.w);
        div1 += w2a;
        acc2.x = fmaf(w2p, xv.x, acc2.x); acc2.y = fmaf(w2p, xv.y, acc2.y);
        acc2.z = fmaf(w2p, xv.z, acc2.z); acc2.w = fmaf(w2p, xv.w, acc2.w);
        div2 += w2p;
        float i1 = 1.f / div1, i2 = 1.f / div2;
        float4 r;
        r.x = eluf(0.5f * (acc1.x * i1 + acc2.x * i2));
        r.y = eluf(0.5f * (acc1.y * i1 + acc2.y * i2));
        r.z = eluf(0.5f * (acc1.z * i1 + acc2.z * i2));
        r.w = eluf(0.5f * (acc1.w * i1 + acc2.w * i2));
        *reinterpret_cast<float4*>(&out[(size_t)n * 64 + (sub << 2)]) = r;
    }
}

// ---------------- final projection: out = h_a @ fc2_w + fc2_b ----------------
__global__ void final_fc2_kernel(const float* __restrict__ W,
                                 const float* __restrict__ b,
                                 float* __restrict__ out, int curA) {
    __shared__ float ws[64 * 16];
    int tid = threadIdx.x;
    for (int i = tid; i < 64 * 16; i += blockDim.x) ws[i] = W[i];
    __syncthreads();
    const float* h = bufA_c(curA);
    int j = tid & 15, nl = tid >> 4;   // 16 nodes per 256-thread block
    for (int n = blockIdx.x * 16 + nl; n < NA; n += gridDim.x * 16) {
        float acc = b[j];
        #pragma unroll 8
        for (int k = 0; k < 64; k++) acc = fmaf(h[(size_t)n * 64 + k], ws[k * 16 + j], acc);
        out[(size_t)n * 16 + j] = acc;
    }
}

// ---------------- launch ----------------
extern "C" void kernel_launch(void* const* d_in, const int* in_sizes, int n_in,
                              void* d_out, int out_size) {
    const float* x_a   = (const float*)d_in[0];
    const float* x_p   = (const float*)d_in[1];
    const int* ap_s    = (const int*)d_in[2];
    const int* ap_t    = (const int*)d_in[3];
    const int* pa_s    = (const int*)d_in[4];
    const int* pa_t    = (const int*)d_in[5];
    const int* pp_s    = (const int*)d_in[6];
    const int* pp_t    = (const int*)d_in[7];
    const float* fc1aw = (const float*)d_in[8];
    const float* fc1ab = (const float*)d_in[9];
    const float* fc1pw = (const float*)d_in[10];
    const float* fc1pb = (const float*)d_in[11];
    const float* fc2w  = (const float*)d_in[12];
    const float* fc2b  = (const float*)d_in[13];
    const float* a1ap  = (const float*)d_in[14];
    const float* a2ap  = (const float*)d_in[15];
    const float* a1pa  = (const float*)d_in[16];
    const float* a2pa  = (const float*)d_in[17];
    const float* a1pp  = (const float*)d_in[18];
    const float* a2pp  = (const float*)d_in[19];
    float* out = (float*)d_out;

    // CSR build (3 edge types, reused across all hops)
    zero_cnt_kernel<<<977, 256>>>();
    hist_kernel<<<6000, 256>>>(ap_s, pa_s, pp_s);
    scan_kernel<<<3, 1024>>>();
    zero_cnt_kernel<<<977, 256>>>();
    scatter_kernel<<<6000, 256>>>(ap_s, ap_t, pa_s, pa_t, pp_s, pp_t);

    // input projections
    proj_gemm_kernel<<<(NA + 63) / 64, 256>>>(x_a, fc1aw, fc1ab, NA, DA, 0);
    proj_gemm_kernel<<<(NP + 63) / 64, 256>>>(x_p, fc1pw, fc1pb, NP, DP, 1);

    int curA = 2, curP = 2, nxt = 0;
    for (int hop = 0; hop < 3; hop++) {
        const float* v1ap = a1ap + 64 * hop;
        const float* v2ap = a2ap + 64 * hop;
        const float* v1pa = a1pa + 64 * hop;
        const float* v2pa = a2pa + 64 * hop;
        const float* v1pp = a1pp + 64 * hop;
        const float* v2pp = a2pp + 64 * hop;
        sprojA_kernel<<<6250, 256>>>(v1ap, v2ap, v2pa, curA);
        sprojP_kernel<<<12500, 256>>>(v1pa, v2pa, v1pp, v2pp, v2ap, curP);
        aggA_kernel<<<3125, 256>>>(curP, nxt);
        aggP_kernel<<<6250, 256>>>(curA, curP, nxt);
        curA = nxt; curP = nxt; nxt ^= 1;
    }

    final_fc2_kernel<<<3125, 256>>>(fc2w, fc2b, out, curA);
}

// round 4
// speedup vs baseline: 1.3095x; 1.3095x over previous
#include <cuda_runtime.h>
#include <cuda_bf16.h>
#include <math.h>

#define NA 50000
#define NP 100000
#define DA 512
#define DP 256
#define HID 64
#define NOUT 16
#define NE 2000000
#define CH 2048
#define NCH_A 25   // ceil(50000/2048)
#define NCH_P 49   // ceil(100000/2048)
#define NBLK_SCAN (NCH_A + 2*NCH_P)   // 123
#define BA_BLOCKS 3125   // NA/2 nodes -> 25000 warps
#define BP_BLOCKS 6250
#define GEMM_A_BLOCKS 391  // ceil(50000/128)
#define GEMM_P_BLOCKS 782  // ceil(100000/128)
#define XS_STRIDE 132      // multiple of 4 so every row is 16B-aligned for LDS.128

// ---------------- scratch ----------------
__device__ float g_xa[NA * HID];
__device__ float g_xp[NP * HID];
__device__ float g_ha[2 * NA * HID];
__device__ float g_hp[2 * NP * HID];

__device__ int g_rp_ap[NA + 1];
__device__ int g_rp_pa[NP + 1];
__device__ int g_rp_pp[NP + 1];
__device__ int g_ts_ap[NE];
__device__ int g_ts_pa[NE];
__device__ int g_ts_pp[NE];
__device__ int g_cntA[NA];
__device__ int g_cntP1[NP];
__device__ int g_cntP2[NP];
__device__ int g_bsum[3 * 64];

// x-based attention scalars, all hops precomputed
__device__ float g_x1ap[3 * NA], g_x2ap[3 * NA];
__device__ float g_x1pa[3 * NP], g_x2pa[3 * NP], g_x1pp[3 * NP], g_x2pp[3 * NP];
// h-based scalars, double buffered
__device__ float g_h1pa[2 * NA];
__device__ float g_h1ap[2 * NP], g_h1pp[2 * NP];

// ---------------- helpers ----------------
__device__ __forceinline__ const float* bufA_c(int c) {
    return (c == 2) ? g_xa : (g_ha + (size_t)c * NA * HID);
}
__device__ __forceinline__ const float* bufP_c(int c) {
    return (c == 2) ? g_xp : (g_hp + (size_t)c * NP * HID);
}
__device__ __forceinline__ float eluf(float v) { return v > 0.f ? v : expm1f(v); }
__device__ __forceinline__ float lrelu_exp(float sc) {
    sc = sc >= 0.f ? sc : 0.2f * sc;
    return __expf(sc);
}
__device__ __forceinline__ float wred32(float v) {
    v += __shfl_down_sync(0xffffffffu, v, 16);
    v += __shfl_down_sync(0xffffffffu, v, 8);
    v += __shfl_down_sync(0xffffffffu, v, 4);
    v += __shfl_down_sync(0xffffffffu, v, 2);
    v += __shfl_down_sync(0xffffffffu, v, 1);
    return v;
}
__device__ __forceinline__ float wred16(float v) {
    v += __shfl_down_sync(0xffffffffu, v, 8, 16);
    v += __shfl_down_sync(0xffffffffu, v, 4, 16);
    v += __shfl_down_sync(0xffffffffu, v, 2, 16);
    v += __shfl_down_sync(0xffffffffu, v, 1, 16);
    return v;
}
__device__ __forceinline__ unsigned long long pk2(float lo, float hi) {
    unsigned long long r;
    asm("mov.b64 %0, {%1, %2};" : "=l"(r) : "f"(lo), "f"(hi));
    return r;
}
__device__ __forceinline__ void up2(unsigned long long v, float& lo, float& hi) {
    asm("mov.b64 {%0, %1}, %2;" : "=f"(lo), "=f"(hi) : "l"(v));
}
__device__ __forceinline__ void ffma2(unsigned long long& d, unsigned long long a, unsigned long long b) {
    asm("fma.rn.f32x2 %0, %1, %2, %0;" : "+l"(d) : "l"(a), "l"(b));
}

// ---------------- CSR build ----------------
__global__ void zero_cnt_kernel() {
    int i = blockIdx.x * blockDim.x + threadIdx.x;
    int stride = gridDim.x * blockDim.x;
    for (; i < NA + 2 * NP; i += stride) {
        if (i < NA) g_cntA[i] = 0;
        else if (i < NA + NP) g_cntP1[i - NA] = 0;
        else g_cntP2[i - NA - NP] = 0;
    }
}

__global__ void hist_kernel(const int* __restrict__ ap_s,
                            const int* __restrict__ pa_s,
                            const int* __restrict__ pp_s) {
    const int Q = NE / 4;   // int4 chunks per relation
    int i = blockIdx.x * blockDim.x + threadIdx.x;
    int stride = gridDim.x * blockDim.x;
    for (; i < 3 * Q; i += stride) {
        int4 v;
        int* cnt;
        if (i < Q)          { v = ((const int4*)ap_s)[i];        cnt = g_cntA;  }
        else if (i < 2 * Q) { v = ((const int4*)pa_s)[i - Q];    cnt = g_cntP1; }
        else                { v = ((const int4*)pp_s)[i - 2 * Q]; cnt = g_cntP2; }
        atomicAdd(&cnt[v.x], 1);
        atomicAdd(&cnt[v.y], 1);
        atomicAdd(&cnt[v.z], 1);
        atomicAdd(&cnt[v.w], 1);
    }
}

__device__ __forceinline__ void rel_of(int b, int& rel, int& chunk) {
    if (b < NCH_A)              { rel = 0; chunk = b; }
    else if (b < NCH_A + NCH_P) { rel = 1; chunk = b - NCH_A; }
    else                        { rel = 2; chunk = b - NCH_A - NCH_P; }
}

__global__ void scan_passA() {
    int rel, chunk; rel_of(blockIdx.x, rel, chunk);
    const int* cnt = rel == 0 ? g_cntA : (rel == 1 ? g_cntP1 : g_cntP2);
    int n = rel == 0 ? NA : NP;
    int base = chunk * CH;
    int s = 0;
    #pragma unroll
    for (int j = 0; j < 8; j++) {
        int i = base + threadIdx.x + 256 * j;
        if (i < n) s += cnt[i];
    }
    #pragma unroll
    for (int o = 16; o; o >>= 1) s += __shfl_down_sync(0xffffffffu, s, o);
    __shared__ int sh[8];
    int lane = threadIdx.x & 31, wid = threadIdx.x >> 5;
    if (lane == 0) sh[wid] = s;
    __syncthreads();
    if (wid == 0) {
        int t = (lane < 8) ? sh[lane] : 0;
        #pragma unroll
        for (int o = 4; o; o >>= 1) t += __shfl_down_sync(0xffffffffu, t, o);
        if (lane == 0) g_bsum[rel * 64 + chunk] = t;
    }
}

__global__ void scan_passB() {   // 1 block, 96 threads
    int wid = threadIdx.x >> 5, lane = threadIdx.x & 31;
    if (wid < 3) {
        int nch = (wid == 0) ? NCH_A : NCH_P;
        int carry = 0;
        #pragma unroll
        for (int c0 = 0; c0 < 64; c0 += 32) {
            int idx = c0 + lane;
            int v = (idx < nch) ? g_bsum[wid * 64 + idx] : 0;
            int x = v;
            #pragma unroll
            for (int o = 1; o < 32; o <<= 1) {
                int y = __shfl_up_sync(0xffffffffu, x, o);
                if (lane >= o) x += y;
            }
            g_bsum[wid * 64 + idx] = carry + x - v;   // exclusive
            carry += __shfl_sync(0xffffffffu, x, 31);
        }
        if (lane == 0) {
            if (wid == 0)      g_rp_ap[NA] = carry;
            else if (wid == 1) g_rp_pa[NP] = carry;
            else               g_rp_pp[NP] = carry;
        }
    }
}

__global__ void scan_passC() {   // re-scan chunk, write rp, zero cnt
    int rel, chunk; rel_of(blockIdx.x, rel, chunk);
    int* cnt; int* rp; int n;
    if (rel == 0)      { cnt = g_cntA;  rp = g_rp_ap; n = NA; }
    else if (rel == 1) { cnt = g_cntP1; rp = g_rp_pa; n = NP; }
    else               { cnt = g_cntP2; rp = g_rp_pp; n = NP; }
    int tid = threadIdx.x, lane = tid & 31, wid = tid >> 5;
    int i0 = chunk * CH + tid * 8;
    int v[8];
    #pragma unroll
    for (int j = 0; j < 8; j++) v[j] = (i0 + j < n) ? cnt[i0 + j] : 0;
    int s = 0;
    #pragma unroll
    for (int j = 0; j < 8; j++) { int t = v[j]; v[j] = s; s += t; }   // local exclusive, s=sum
    int x = s;
    #pragma unroll
    for (int o = 1; o < 32; o <<= 1) {
        int y = __shfl_up_sync(0xffffffffu, x, o);
        if (lane >= o) x += y;
    }
    __shared__ int wsum[8];
    if (lane == 31) wsum[wid] = x;
    __syncthreads();
    if (wid == 0 && lane < 8) {
        int t = wsum[lane];
        int xx = t;
        #pragma unroll
        for (int o = 1; o < 8; o <<= 1) {
            int y = __shfl_up_sync(0xffu, xx, o);
            if (lane >= o) xx += y;
        }
        wsum[lane] = xx - t;   // exclusive warp offsets
    }
    __syncthreads();
    int off = g_bsum[rel * 64 + chunk] + wsum[wid] + (x - s);
    #pragma unroll
    for (int j = 0; j < 8; j++) {
        int i = i0 + j;
        if (i < n) { rp[i] = off + v[j]; cnt[i] = 0; }
    }
}

__global__ void scatter_kernel(const int* __restrict__ ap_s, const int* __restrict__ ap_t,
                               const int* __restrict__ pa_s, const int* __restrict__ pa_t,
                               const int* __restrict__ pp_s, const int* __restrict__ pp_t) {
    int i = blockIdx.x * blockDim.x + threadIdx.x;
    int stride = gridDim.x * blockDim.x;
    for (; i < 3 * NE; i += stride) {
        if (i < NE) {
            int s = ap_s[i];
            int pos = g_rp_ap[s] + atomicAdd(&g_cntA[s], 1);
            g_ts_ap[pos] = ap_t[i];
        } else if (i < 2 * NE) {
            int e = i - NE;
            int s = pa_s[e];
            int pos = g_rp_pa[s] + atomicAdd(&g_cntP1[s], 1);
            g_ts_pa[pos] = pa_t[e];
        } else {
            int e = i - 2 * NE;
            int s = pp_s[e];
            int pos = g_rp_pp[s] + atomicAdd(&g_cntP2[s], 1);
            g_ts_pp[pos] = pp_t[e];
        }
    }
}

// ---------------- projection GEMM, 128 threads, 128x64 tile, 8x8/thread, FFMA2 ----
__global__ __launch_bounds__(128) void proj_gemm2(
    const float* __restrict__ XA, const float* __restrict__ WA, const float* __restrict__ bA,
    const float* __restrict__ XP, const float* __restrict__ WP, const float* __restrict__ bP) {
    __shared__ __align__(16) float xs[32 * XS_STRIDE];
    __shared__ __align__(16) float ws[32 * 64];
    int b = blockIdx.x;
    const float* X; const float* W; const float* bias; float* Y; int N, K, nb;
    if (b < GEMM_A_BLOCKS) { X = XA; W = WA; bias = bA; Y = g_xa; N = NA; K = DA; nb = b * 128; }
    else { b -= GEMM_A_BLOCKS; X = XP; W = WP; bias = bP; Y = g_xp; N = NP; K = DP; nb = b * 128; }

    int tid = threadIdx.x;
    int tn = tid & 7, tm = tid >> 3;

    unsigned long long acc[8][4];
    #pragma unroll
    for (int r = 0; r < 8; r++)
        #pragma unroll
        for (int p = 0; p < 4; p++) acc[r][p] = 0ull;

    for (int kc = 0; kc < K; kc += 32) {
        #pragma unroll
        for (int j = 0; j < 8; j++) {
            int idx = tid + 128 * j;
            int node = idx >> 3, kq = idx & 7;
            int gn = nb + node;
            float4 v = (gn < N) ? *(const float4*)&X[(size_t)gn * K + kc + kq * 4]
                                : make_float4(0.f, 0.f, 0.f, 0.f);
            int kb = kq * 4;
            xs[(kb + 0) * XS_STRIDE + node] = v.x;
            xs[(kb + 1) * XS_STRIDE + node] = v.y;
            xs[(kb + 2) * XS_STRIDE + node] = v.z;
            xs[(kb + 3) * XS_STRIDE + node] = v.w;
        }
        #pragma unroll
        for (int j = 0; j < 4; j++) {
            int idx = tid + 128 * j;
            int row = idx >> 4, cq = idx & 15;
            *(float4*)&ws[row * 64 + cq * 4] = *(const float4*)&W[(size_t)(kc + row) * 64 + cq * 4];
        }
        __syncthreads();
        #pragma unroll
        for (int kk = 0; kk < 32; kk++) {
            float4 xv0 = *(const float4*)&xs[kk * XS_STRIDE + tm * 4];
            float4 xv1 = *(const float4*)&xs[kk * XS_STRIDE + 64 + tm * 4];
            float4 wv0 = *(const float4*)&ws[kk * 64 + tn * 4];
            float4 wv1 = *(const float4*)&ws[kk * 64 + 32 + tn * 4];
            unsigned long long wp0 = pk2(wv0.x, wv0.y);
            unsigned long long wp1 = pk2(wv0.z, wv0.w);
            unsigned long long wp2 = pk2(wv1.x, wv1.y);
            unsigned long long wp3 = pk2(wv1.z, wv1.w);
            float xr[8] = {xv0.x, xv0.y, xv0.z, xv0.w, xv1.x, xv1.y, xv1.z, xv1.w};
            #pragma unroll
            for (int r = 0; r < 8; r++) {
                unsigned long long xd = pk2(xr[r], xr[r]);
                ffma2(acc[r][0], xd, wp0);
                ffma2(acc[r][1], xd, wp1);
                ffma2(acc[r][2], xd, wp2);
                ffma2(acc[r][3], xd, wp3);
            }
        }
        __syncthreads();
    }

    float4 bv0 = *(const float4*)&bias[tn * 4];
    float4 bv1 = *(const float4*)&bias[32 + tn * 4];
    #pragma unroll
    for (int r = 0; r < 8; r++) {
        int node = nb + ((r < 4) ? (tm * 4 + r) : (64 + tm * 4 + r - 4));
        if (node < N) {
            float f0, f1, f2, f3, f4, f5, f6, f7;
            up2(acc[r][0], f0, f1);
            up2(acc[r][1], f2, f3);
            up2(acc[r][2], f4, f5);
            up2(acc[r][3], f6, f7);
            float4 o0, o1;
            o0.x = fmaxf(f0 + bv0.x, 0.f); o0.y = fmaxf(f1 + bv0.y, 0.f);
            o0.z = fmaxf(f2 + bv0.z, 0.f); o0.w = fmaxf(f3 + bv0.w, 0.f);
            o1.x = fmaxf(f4 + bv1.x, 0.f); o1.y = fmaxf(f5 + bv1.y, 0.f);
            o1.z = fmaxf(f6 + bv1.z, 0.f); o1.w = fmaxf(f7 + bv1.w, 0.f);
            *(float4*)&Y[(size_t)node * 64 + tn * 4] = o0;
            *(float4*)&Y[(size_t)node * 64 + 32 + tn * 4] = o1;
        }
    }
}

// ---------------- upfront scalar projections (all hops, x-based + hop-0 h-based) ----
__global__ void sproj0_kernel(const float* __restrict__ a1ap, const float* __restrict__ a2ap,
                              const float* __restrict__ a1pa, const float* __restrict__ a2pa,
                              const float* __restrict__ a1pp, const float* __restrict__ a2pp) {
    int gw = (blockIdx.x * blockDim.x + threadIdx.x) >> 5;
    int lane = threadIdx.x & 31;
    if (gw < NA) {
        int n = gw;
        float x0 = g_xa[(size_t)n * 64 + lane], x1 = g_xa[(size_t)n * 64 + 32 + lane];
        #pragma unroll
        for (int h = 0; h < 3; h++) {
            float d1 = wred32(fmaf(x0, a1ap[h * 64 + lane], x1 * a1ap[h * 64 + 32 + lane]));
            float d2 = wred32(fmaf(x0, a2ap[h * 64 + lane], x1 * a2ap[h * 64 + 32 + lane]));
            if (lane == 0) { g_x1ap[h * NA + n] = d1; g_x2ap[h * NA + n] = d2; }
        }
        float d3 = wred32(fmaf(x0, a2pa[lane], x1 * a2pa[32 + lane]));
        if (lane == 0) g_h1pa[n] = d3;   // buffer 0
    } else {
        int n = gw - NA;
        float x0 = g_xp[(size_t)n * 64 + lane], x1 = g_xp[(size_t)n * 64 + 32 + lane];
        #pragma unroll
        for (int h = 0; h < 3; h++) {
            float d1 = wred32(fmaf(x0, a1pa[h * 64 + lane], x1 * a1pa[h * 64 + 32 + lane]));
            float d2 = wred32(fmaf(x0, a2pa[h * 64 + lane], x1 * a2pa[h * 64 + 32 + lane]));
            float d3 = wred32(fmaf(x0, a1pp[h * 64 + lane], x1 * a1pp[h * 64 + 32 + lane]));
            float d4 = wred32(fmaf(x0, a2pp[h * 64 + lane], x1 * a2pp[h * 64 + 32 + lane]));
            if (lane == 0) {
                g_x1pa[h * NP + n] = d1; g_x2pa[h * NP + n] = d2;
                g_x1pp[h * NP + n] = d3; g_x2pp[h * NP + n] = d4;
            }
        }
        float d5 = wred32(fmaf(x0, a2ap[lane], x1 * a2ap[32 + lane]));
        float d6 = wred32(fmaf(x0, a2pp[lane], x1 * a2pp[32 + lane]));
        if (lane == 0) { g_h1ap[n] = d5; g_h1pp[n] = d6; }   // buffer 0
    }
}

// ---------------- merged edge aggregation ----------------
__device__ __forceinline__ void relation_accum(const int* __restrict__ rp,
                                               const int* __restrict__ ts,
                                               const float* __restrict__ h,
                                               const float* __restrict__ h1arr,
                                               float x1, int n, int sub,
                                               float4& acc, float& div) {
    int e = rp[n], end = rp[n + 1];
    #pragma unroll 4
    for (; e < end; ++e) {
        int t = __ldg(&ts[e]);
        float w = lrelu_exp(x1 + __ldg(&h1arr[t]));
        const float4 hv = *reinterpret_cast<const float4*>(&h[(size_t)t * 64 + (sub << 2)]);
        acc.x = fmaf(w, hv.x, acc.x);
        acc.y = fmaf(w, hv.y, acc.y);
        acc.z = fmaf(w, hv.z, acc.z);
        acc.w = fmaf(w, hv.w, acc.w);
        div += w;
    }
}

__global__ void agg_kernel(int curA, int curP, int nxt, int h1cur, int h1nxt, int hop, int last,
                           const float* __restrict__ a2pa_nx,
                           const float* __restrict__ a2ap_nx,
                           const float* __restrict__ a2pp_nx) {
    int lane = threadIdx.x & 31;
    int sub = lane & 15;
    int half = lane >> 4;
    if (blockIdx.x < BA_BLOCKS) {
        int warp = (blockIdx.x * blockDim.x + threadIdx.x) >> 5;
        int n = warp * 2 + half;            // exact cover of NA
        const float* __restrict__ h = bufP_c(curP);
        const float* __restrict__ h1 = g_h1ap + (size_t)h1cur * NP;
        float* __restrict__ out = g_ha + (size_t)nxt * NA * HID;
        float x1 = g_x1ap[hop * NA + n];
        float4 acc = {0.f, 0.f, 0.f, 0.f};
        float div = 0.f;
        relation_accum(g_rp_ap, g_ts_ap, h, h1, x1, n, sub, acc, div);
        float w2 = lrelu_exp(x1 + g_x2ap[hop * NA + n]);
        const float4 xv = *reinterpret_cast<const float4*>(&g_xa[(size_t)n * 64 + (sub << 2)]);
        acc.x = fmaf(w2, xv.x, acc.x); acc.y = fmaf(w2, xv.y, acc.y);
        acc.z = fmaf(w2, xv.z, acc.z); acc.w = fmaf(w2, xv.w, acc.w);
        div += w2;
        float inv = 1.f / div;
        float4 r;
        r.x = eluf(acc.x * inv); r.y = eluf(acc.y * inv);
        r.z = eluf(acc.z * inv); r.w = eluf(acc.w * inv);
        *reinterpret_cast<float4*>(&out[(size_t)n * 64 + (sub << 2)]) = r;
        if (!last) {
            const float4 va = *(const float4*)&a2pa_nx[sub << 2];
            float p = r.x * va.x + r.y * va.y + r.z * va.z + r.w * va.w;
            p = wred16(p);
            if (sub == 0) g_h1pa[(size_t)h1nxt * NA + n] = p;
        }
    } else {
        int warp = ((blockIdx.x - BA_BLOCKS) * blockDim.x + threadIdx.x) >> 5;
        int n = warp * 2 + half;            // exact cover of NP
        const float* __restrict__ hA = bufA_c(curA);
        const float* __restrict__ hP = bufP_c(curP);
        const float* __restrict__ h1a = g_h1pa + (size_t)h1cur * NA;
        const float* __restrict__ h1p = g_h1pp + (size_t)h1cur * NP;
        float* __restrict__ out = g_hp + (size_t)nxt * NP * HID;
        float x1a = g_x1pa[hop * NP + n];
        float x1p = g_x1pp[hop * NP + n];
        float4 acc1 = {0.f, 0.f, 0.f, 0.f}, acc2 = {0.f, 0.f, 0.f, 0.f};
        float div1 = 0.f, div2 = 0.f;
        relation_accum(g_rp_pa, g_ts_pa, hA, h1a, x1a, n, sub, acc1, div1);
        relation_accum(g_rp_pp, g_ts_pp, hP, h1p, x1p, n, sub, acc2, div2);
        const float4 xv = *reinterpret_cast<const float4*>(&g_xp[(size_t)n * 64 + (sub << 2)]);
        float w2a = lrelu_exp(x1a + g_x2pa[hop * NP + n]);
        float w2p = lrelu_exp(x1p + g_x2pp[hop * NP + n]);
        acc1.x = fmaf(w2a, xv.x, acc1.x); acc1.y = fmaf(w2a, xv.y, acc1.y);
        acc1.z = fmaf(w2a, xv.z, acc1.z); acc1.w = fmaf(w2a, xv.w, acc1.w);
        div1 += w2a;
        acc2.x = fmaf(w2p, xv.x, acc2.x); acc2.y = fmaf(w2p, xv.y, acc2.y);
        acc2.z = fmaf(w2p, xv.z, acc2.z); acc2.w = fmaf(w2p, xv.w, acc2.w);
        div2 += w2p;
        float i1 = 1.f / div1, i2 = 1.f / div2;
        float4 r;
        r.x = eluf(0.5f * (acc1.x * i1 + acc2.x * i2));
        r.y = eluf(0.5f * (acc1.y * i1 + acc2.y * i2));
        r.z = eluf(0.5f * (acc1.z * i1 + acc2.z * i2));
        r.w = eluf(0.5f * (acc1.w * i1 + acc2.w * i2));
        *reinterpret_cast<float4*>(&out[(size_t)n * 64 + (sub << 2)]) = r;
        if (!last) {
            const float4 va = *(const float4*)&a2ap_nx[sub << 2];
            const float4 vp = *(const float4*)&a2pp_nx[sub << 2];
            float p1 = r.x * va.x + r.y * va.y + r.z * va.z + r.w * va.w;
            float p2 = r.x * vp.x + r.y * vp.y + r.z * vp.z + r.w * vp.w;
            p1 = wred16(p1);
            p2 = wred16(p2);
            if (sub == 0) {
                g_h1ap[(size_t)h1nxt * NP + n] = p1;
                g_h1pp[(size_t)h1nxt * NP + n] = p2;
            }
        }
    }
}

// ---------------- final projection ----------------
__global__ void final_fc2_kernel(const float* __restrict__ W,
                                 const float* __restrict__ b,
                                 float* __restrict__ out, int curA) {
    __shared__ float ws[64 * 16];
    int tid = threadIdx.x;
    for (int i = tid; i < 64 * 16; i += blockDim.x) ws[i] = W[i];
    __syncthreads();
    const float* h = bufA_c(curA);
    int j = tid & 15, nl = tid >> 4;
    for (int n = blockIdx.x * 16 + nl; n < NA; n += gridDim.x * 16) {
        float acc = b[j];
        #pragma unroll 8
        for (int k = 0; k < 64; k++) acc = fmaf(h[(size_t)n * 64 + k], ws[k * 16 + j], acc);
        out[(size_t)n * 16 + j] = acc;
    }
}

// ---------------- launch ----------------
extern "C" void kernel_launch(void* const* d_in, const int* in_sizes, int n_in,
                              void* d_out, int out_size) {
    const float* x_a   = (const float*)d_in[0];
    const float* x_p   = (const float*)d_in[1];
    const int* ap_s    = (const int*)d_in[2];
    const int* ap_t    = (const int*)d_in[3];
    const int* pa_s    = (const int*)d_in[4];
    const int* pa_t    = (const int*)d_in[5];
    const int* pp_s    = (const int*)d_in[6];
    const int* pp_t    = (const int*)d_in[7];
    const float* fc1aw = (const float*)d_in[8];
    const float* fc1ab = (const float*)d_in[9];
    const float* fc1pw = (const float*)d_in[10];
    const float* fc1pb = (const float*)d_in[11];
    const float* fc2w  = (const float*)d_in[12];
    const float* fc2b  = (const float*)d_in[13];
    const float* a1ap  = (const float*)d_in[14];
    const float* a2ap  = (const float*)d_in[15];
    const float* a1pa  = (const float*)d_in[16];
    const float* a2pa  = (const float*)d_in[17];
    const float* a1pp  = (const float*)d_in[18];
    const float* a2pp  = (const float*)d_in[19];
    float* out = (float*)d_out;

    // CSR build
    zero_cnt_kernel<<<977, 256>>>();
    hist_kernel<<<1024, 256>>>(ap_s, pa_s, pp_s);
    scan_passA<<<NBLK_SCAN, 256>>>();
    scan_passB<<<1, 96>>>();
    scan_passC<<<NBLK_SCAN, 256>>>();   // also zeroes cnt
    scatter_kernel<<<6000, 256>>>(ap_s, ap_t, pa_s, pa_t, pp_s, pp_t);

    // input projections (merged A+P)
    proj_gemm2<<<GEMM_A_BLOCKS + GEMM_P_BLOCKS, 128>>>(x_a, fc1aw, fc1ab, x_p, fc1pw, fc1pb);

    // all-hop x-based scalars + hop-0 h-based scalars
    sproj0_kernel<<<(NA + NP) / 8, 256>>>(a1ap, a2ap, a1pa, a2pa, a1pp, a2pp);

    // hops
    int curA = 2, curP = 2, nxt = 0, h1cur = 0, h1nxt = 1;
    for (int hop = 0; hop < 3; hop++) {
        int last = (hop == 2);
        int nh = last ? 2 : (hop + 1);   // next-hop index for a2 vectors (unused when last)
        agg_kernel<<<BA_BLOCKS + BP_BLOCKS, 256>>>(curA, curP, nxt, h1cur, h1nxt, hop, last,
                                                   a2pa + 64 * nh, a2ap + 64 * nh, a2pp + 64 * nh);
        curA = nxt; curP = nxt;
        nxt ^= 1;
        int t = h1cur; h1cur = h1nxt; h1nxt = t;
    }

    final_fc2_kernel<<<3125, 256>>>(fc2w, fc2b, out, curA);
}